// round 4
// baseline (speedup 1.0000x reference)
#include <cuda_runtime.h>
#include <cuda_fp16.h>
#include <mma.h>

using namespace nvcuda;

static constexpr int   T = 262144;
static constexpr int   S = 128;
static constexpr int   H = 1024;
static constexpr int   A = 16;
static constexpr float GAMMA = 0.99f;
static constexpr float EPSC  = 0.2f;
static constexpr float LOG_SQRT_2PI = 0.91893853320467274178f;

// ---------------- scratch (no allocation allowed) ----------------
__device__ float g_adv[T];
__device__ float g_blockA[256];
__device__ float g_blockB[256];
__device__ float g_blockInc[256];
__device__ float g_s1, g_s2, g_actor;
__device__ float g_mean, g_inv, g_critic;

// ---------------- small helpers ----------------
__device__ __forceinline__ float tanh_fast(float x) {
    float y;
    asm("tanh.approx.f32 %0, %1;" : "=f"(y) : "f"(x));
    return y;
}

__device__ __forceinline__ float block_reduce_256(float v, float* red8) {
    #pragma unroll
    for (int o = 16; o > 0; o >>= 1) v += __shfl_down_sync(0xffffffffu, v, o);
    if ((threadIdx.x & 31) == 0) red8[threadIdx.x >> 5] = v;
    __syncthreads();
    if (threadIdx.x < 8) {
        v = red8[threadIdx.x];
        #pragma unroll
        for (int o = 4; o > 0; o >>= 1) v += __shfl_down_sync(0xffu, v, o);
    }
    return v;  // valid in thread 0
}

// ---------------- K0: zero accumulators ----------------
__global__ void k_zero() { g_s1 = 0.f; g_s2 = 0.f; g_actor = 0.f; }

// ---------------- K1: per-block affine composition of the reversed scan ----------------
// ret[i] = r[i] + (gamma*m[i]) * ret[i+1]; block transform x -> A*x + B
__global__ void k_scan1(const float* __restrict__ rewards, const int* __restrict__ masks) {
    int blk = blockIdx.x, tid = threadIdx.x;
    int base = blk * 1024 + tid * 4;
    float4 r = *(const float4*)(rewards + base);
    int4   m = *(const int4*)(masks + base);
    float a = 1.f, b = 0.f, c;
    c = GAMMA * (float)m.w; b = r.w + c * b; a *= c;
    c = GAMMA * (float)m.z; b = r.z + c * b; a *= c;
    c = GAMMA * (float)m.y; b = r.y + c * b; a *= c;
    c = GAMMA * (float)m.x; b = r.x + c * b; a *= c;
    __shared__ float sa[256], sb[256];
    sa[tid] = a; sb[tid] = b;
    __syncthreads();
    if (tid == 0) {
        float Ab = 1.f, Bb = 0.f;
        for (int t = 255; t >= 0; --t) { Bb = sb[t] + sa[t] * Bb; Ab = sa[t] * Ab; }
        g_blockA[blk] = Ab; g_blockB[blk] = Bb;
    }
}

// ---------------- K2: scan the 256 block summaries (right to left) ----------------
__global__ void k_scan2() {
    __shared__ float sa[256], sb[256], sinc[256];
    int tid = threadIdx.x;
    sa[tid] = g_blockA[tid]; sb[tid] = g_blockB[tid];
    __syncthreads();
    if (tid == 0) {
        float x = 0.f;
        for (int b = 255; b >= 0; --b) { sinc[b] = x; x = sb[b] + sa[b] * x; }
    }
    __syncthreads();
    g_blockInc[tid] = sinc[tid];
}

// ---------------- K3: apply scan, compute adv, accumulate sums ----------------
__global__ void k_scan3(const float* __restrict__ rewards, const int* __restrict__ masks,
                        const float* __restrict__ values) {
    int blk = blockIdx.x, tid = threadIdx.x;
    int base = blk * 1024 + tid * 4;
    float4 r = *(const float4*)(rewards + base);
    int4   m = *(const int4*)(masks + base);
    float c0 = GAMMA * (float)m.x, c1 = GAMMA * (float)m.y;
    float c2 = GAMMA * (float)m.z, c3 = GAMMA * (float)m.w;
    float a = 1.f, b = 0.f;
    b = r.w + c3 * b; a *= c3;
    b = r.z + c2 * b; a *= c2;
    b = r.y + c1 * b; a *= c1;
    b = r.x + c0 * b; a *= c0;
    __shared__ float sa[256], sb[256], sinc[256];
    __shared__ float red8[8];
    sa[tid] = a; sb[tid] = b;
    __syncthreads();
    if (tid == 0) {
        float x = g_blockInc[blk];
        for (int t = 255; t >= 0; --t) { sinc[t] = x; x = sb[t] + sa[t] * x; }
    }
    __syncthreads();
    float x = sinc[tid];
    float ret3 = r.w + c3 * x;
    float ret2 = r.z + c2 * ret3;
    float ret1 = r.y + c1 * ret2;
    float ret0 = r.x + c0 * ret1;
    float4 v = *(const float4*)(values + base);
    float4 adv = make_float4(ret0 - v.x, ret1 - v.y, ret2 - v.z, ret3 - v.w);
    *(float4*)(g_adv + base) = adv;
    float s1 = adv.x + adv.y + adv.z + adv.w;
    float s2 = adv.x * adv.x + adv.y * adv.y + adv.z * adv.z + adv.w * adv.w;
    float t1 = block_reduce_256(s1, red8);
    __syncthreads();
    float t2 = block_reduce_256(s2, red8);
    if (tid == 0) { atomicAdd(&g_s1, t1); atomicAdd(&g_s2, t2); }
}

// ---------------- K4: stats ----------------
__global__ void k_stats() {
    float s1 = g_s1, s2 = g_s2;
    float mean = s1 / (float)T;
    float var  = (s2 - s1 * mean) / (float)(T - 1);
    g_mean = mean;
    g_inv  = 1.f / (sqrtf(var) + 1e-7f);
    g_critic = s2 / (float)T;
}

// ---------------- K5: fused policy-net + PPO actor loss ----------------
static constexpr int RT = 256;       // rows per CTA tile
static constexpr int NH = 64;        // H chunk
static constexpr int NCHUNK = H / NH;
static constexpr int LDA = 136;      // half elems
static constexpr int LDW = 72;
static constexpr int LDP = 72;
static constexpr int LDMU = 20;      // float elems (reduces epilogue bank conflicts)

static constexpr int SM_A   = 0;
static constexpr int SM_W1  = SM_A   + RT * LDA * 2;       // 69632
static constexpr int SM_P   = SM_W1  + 128 * LDW * 2;      // 88064
static constexpr int SM_TMP = SM_P   + RT * LDP * 2;       // 124928
static constexpr int SM_WMU = SM_TMP + 8 * 256 * 4;        // 133120
static constexpr int SM_WLV = SM_WMU + 64 * 16 * 2;        // 135168
static constexpr int SM_B1  = SM_WLV + 64 * 16 * 2;        // 137216
static constexpr int SM_TOTAL = SM_B1 + 64 * 4;            // 137472

__global__ __launch_bounds__(256, 1)
void k_main(const float* __restrict__ states, const float* __restrict__ actions,
            const float* __restrict__ blp,
            const float* __restrict__ W1, const float* __restrict__ b1,
            const float* __restrict__ Wmu, const float* __restrict__ bmu,
            const float* __restrict__ Wlv, const float* __restrict__ blv) {
    extern __shared__ char smem[];
    half*  sA   = (half*)(smem + SM_A);
    half*  sW1  = (half*)(smem + SM_W1);
    half*  sP   = (half*)(smem + SM_P);
    float* sTmp = (float*)(smem + SM_TMP);
    half*  sWmu = (half*)(smem + SM_WMU);
    half*  sWlv = (half*)(smem + SM_WLV);
    float* sB1  = (float*)(smem + SM_B1);
    float* sMu  = (float*)(smem + SM_A);        // overlays sA after chunk loop
    float* sLv  = sMu + RT * LDMU;
    __shared__ float red8[8];

    int tid  = threadIdx.x;
    int warp = tid >> 5, lane = tid & 31;
    int r0   = blockIdx.x * RT;

    // load states tile [256 x 128] -> fp16
    #pragma unroll
    for (int it = 0; it < 32; ++it) {
        int idx = tid + 256 * it;           // 8192 float4
        int row = idx >> 5;                 // 32 float4 per row
        int c4  = idx & 31;
        float4 v = *(const float4*)(states + (size_t)(r0 + row) * S + c4 * 4);
        half2* dst = (half2*)(sA + row * LDA + c4 * 4);
        dst[0] = __floats2half2_rn(v.x, v.y);
        dst[1] = __floats2half2_rn(v.z, v.w);
    }

    wmma::fragment<wmma::accumulator, 16, 16, 16, float> accMu[2], accLv[2];
    wmma::fill_fragment(accMu[0], 0.f); wmma::fill_fragment(accMu[1], 0.f);
    wmma::fill_fragment(accLv[0], 0.f); wmma::fill_fragment(accLv[1], 0.f);

    for (int ch = 0; ch < NCHUNK; ++ch) {
        __syncthreads();   // protect sW1/sWmu/sWlv from previous-iteration readers
        // W1 chunk [128 x 64] -> fp16
        #pragma unroll
        for (int it = 0; it < 8; ++it) {
            int idx = tid + 256 * it;       // 2048 float4
            int row = idx >> 4;
            int c4  = idx & 15;
            float4 v = *(const float4*)(W1 + (size_t)row * H + ch * NH + c4 * 4);
            half2* dst = (half2*)(sW1 + row * LDW + c4 * 4);
            dst[0] = __floats2half2_rn(v.x, v.y);
            dst[1] = __floats2half2_rn(v.z, v.w);
        }
        // W_mu / W_lv chunks [64 x 16]
        {
            int row = tid >> 2, c4 = tid & 3;
            float4 v = *(const float4*)(Wmu + (size_t)(ch * NH + row) * A + c4 * 4);
            half2* dm = (half2*)(sWmu + row * 16 + c4 * 4);
            dm[0] = __floats2half2_rn(v.x, v.y);
            dm[1] = __floats2half2_rn(v.z, v.w);
            float4 u = *(const float4*)(Wlv + (size_t)(ch * NH + row) * A + c4 * 4);
            half2* dl = (half2*)(sWlv + row * 16 + c4 * 4);
            dl[0] = __floats2half2_rn(u.x, u.y);
            dl[1] = __floats2half2_rn(u.z, u.w);
        }
        if (tid < 64) sB1[tid] = b1[ch * NH + tid];
        __syncthreads();

        // GEMM1: P = tanh(states @ W1chunk + b1chunk)  [256 x 64]
        #pragma unroll
        for (int j = 0; j < 8; ++j) {
            int tt = warp + 8 * j;
            int tr = tt & 15, tc = tt >> 4;
            wmma::fragment<wmma::accumulator, 16, 16, 16, float> acc;
            wmma::fill_fragment(acc, 0.f);
            #pragma unroll
            for (int k = 0; k < 8; ++k) {
                wmma::fragment<wmma::matrix_a, 16, 16, 16, half, wmma::row_major> fa;
                wmma::fragment<wmma::matrix_b, 16, 16, 16, half, wmma::row_major> fb;
                wmma::load_matrix_sync(fa, sA + tr * 16 * LDA + k * 16, LDA);
                wmma::load_matrix_sync(fb, sW1 + k * 16 * LDW + tc * 16, LDW);
                wmma::mma_sync(acc, fa, fb, acc);
            }
            wmma::store_matrix_sync(sTmp + warp * 256, acc, 16, wmma::mem_row_major);
            __syncwarp();
            #pragma unroll
            for (int i = 0; i < 8; ++i) {
                int pos = lane + 32 * i;
                int rr = pos >> 4, cc = pos & 15;
                float v = sTmp[warp * 256 + pos] + sB1[tc * 16 + cc];
                sP[(tr * 16 + rr) * LDP + tc * 16 + cc] = __float2half_rn(tanh_fast(v));
            }
            __syncwarp();
        }
        __syncthreads();   // sP complete

        // GEMM2: mu/lv += P @ Wchunk   [256 x 16]
        #pragma unroll
        for (int q = 0; q < 2; ++q) {
            int rt2 = warp * 2 + q;
            #pragma unroll
            for (int k = 0; k < 4; ++k) {
                wmma::fragment<wmma::matrix_a, 16, 16, 16, half, wmma::row_major> fa;
                wmma::fragment<wmma::matrix_b, 16, 16, 16, half, wmma::row_major> fb;
                wmma::load_matrix_sync(fa, sP + rt2 * 16 * LDP + k * 16, LDP);
                wmma::load_matrix_sync(fb, sWmu + k * 16 * 16, 16);
                wmma::mma_sync(accMu[q], fa, fb, accMu[q]);
                wmma::load_matrix_sync(fb, sWlv + k * 16 * 16, 16);
                wmma::mma_sync(accLv[q], fa, fb, accLv[q]);
            }
        }
    }
    __syncthreads();

    // dump mu/lv to smem (overlaying sA, which is dead now)
    #pragma unroll
    for (int q = 0; q < 2; ++q) {
        int rt2 = warp * 2 + q;
        wmma::store_matrix_sync(sMu + rt2 * 16 * LDMU, accMu[q], LDMU, wmma::mem_row_major);
        wmma::store_matrix_sync(sLv + rt2 * 16 * LDMU, accLv[q], LDMU, wmma::mem_row_major);
    }
    if (tid < 16) { sTmp[tid] = bmu[tid]; sTmp[16 + tid] = blv[tid]; }
    __syncthreads();

    // epilogue: one row per thread
    int gr = r0 + tid;
    const float4* a4 = (const float4*)(actions + (size_t)gr * A);
    const float4* p4 = (const float4*)(blp + (size_t)gr * A);
    float lsum = 0.f;
    #pragma unroll
    for (int q = 0; q < 4; ++q) {
        float4 av = a4[q];
        float4 bv = p4[q];
        float aarr[4] = {av.x, av.y, av.z, av.w};
        float barr[4] = {bv.x, bv.y, bv.z, bv.w};
        #pragma unroll
        for (int j = 0; j < 4; ++j) {
            int col = q * 4 + j;
            float mu = sMu[tid * LDMU + col] + sTmp[col];
            float lv = sLv[tid * LDMU + col] + sTmp[16 + col];
            float d  = aarr[j] - mu;
            float logp = -0.5f * d * d * __expf(-lv) - 0.5f * lv - LOG_SQRT_2PI;
            lsum += logp - barr[j];
        }
    }
    float ratio = __expf(lsum);
    float ahat  = (g_adv[gr] - g_mean) * g_inv;
    float rc    = fminf(fmaxf(ratio, 1.f - EPSC), 1.f + EPSC);
    float term  = fminf(ratio * ahat, rc * ahat);

    float bsum = block_reduce_256(term, red8);
    if (tid == 0) atomicAdd(&g_actor, bsum);
}

// ---------------- K6: final scalar ----------------
__global__ void k_final(float* out) {
    out[0] = g_critic - g_actor / (float)T;
}

// ---------------- launch ----------------
extern "C" void kernel_launch(void* const* d_in, const int* in_sizes, int n_in,
                              void* d_out, int out_size) {
    const float* states  = (const float*)d_in[0];
    const float* actions = (const float*)d_in[1];
    const float* rewards = (const float*)d_in[2];
    const float* values  = (const float*)d_in[3];
    const float* blp     = (const float*)d_in[4];
    const float* W1      = (const float*)d_in[5];
    const float* b1      = (const float*)d_in[6];
    const float* Wmu     = (const float*)d_in[7];
    const float* bmu     = (const float*)d_in[8];
    const float* Wlv     = (const float*)d_in[9];
    const float* blv     = (const float*)d_in[10];
    const int*   masks   = (const int*)d_in[11];

    cudaFuncSetAttribute(k_main, cudaFuncAttributeMaxDynamicSharedMemorySize, SM_TOTAL);

    k_zero<<<1, 1>>>();
    k_scan1<<<256, 256>>>(rewards, masks);
    k_scan2<<<1, 256>>>();
    k_scan3<<<256, 256>>>(rewards, masks, values);
    k_stats<<<1, 1>>>();
    k_main<<<T / RT, 256, SM_TOTAL>>>(states, actions, blp, W1, b1, Wmu, bmu, Wlv, blv);
    k_final<<<1, 1>>>((float*)d_out);
}

// round 5
// speedup vs baseline: 1.0009x; 1.0009x over previous
#include <cuda_runtime.h>
#include <cuda_fp16.h>
#include <mma.h>

using namespace nvcuda;

static constexpr int   T = 262144;
static constexpr int   S = 128;
static constexpr int   H = 1024;
static constexpr int   A = 16;
static constexpr float GAMMA = 0.99f;
static constexpr float EPSC  = 0.2f;
static constexpr float LOG_SQRT_2PI = 0.91893853320467274178f;

// ---------------- scratch (no allocation allowed) ----------------
__device__ float g_adv[T];
__device__ float g_blockA[256];
__device__ float g_blockB[256];
__device__ float g_blockInc[256];
__device__ float g_s1, g_s2, g_actor;
__device__ float g_mean, g_inv, g_critic;

// ---------------- small helpers ----------------
__device__ __forceinline__ float tanh_fast(float x) {
    float y;
    asm("tanh.approx.f32 %0, %1;" : "=f"(y) : "f"(x));
    return y;
}

__device__ __forceinline__ float block_reduce_256(float v, float* red8) {
    #pragma unroll
    for (int o = 16; o > 0; o >>= 1) v += __shfl_down_sync(0xffffffffu, v, o);
    if ((threadIdx.x & 31) == 0) red8[threadIdx.x >> 5] = v;
    __syncthreads();
    if (threadIdx.x < 8) {
        v = red8[threadIdx.x];
        #pragma unroll
        for (int o = 4; o > 0; o >>= 1) v += __shfl_down_sync(0xffu, v, o);
    }
    return v;  // valid in thread 0
}

// ---------------- K0: zero accumulators ----------------
__global__ void k_zero() { g_s1 = 0.f; g_s2 = 0.f; g_actor = 0.f; }

// ---------------- K1: per-block affine composition of the reversed scan ----------------
// ret[i] = r[i] + (gamma*m[i]) * ret[i+1]; block transform x -> A*x + B
__global__ void k_scan1(const float* __restrict__ rewards, const int* __restrict__ masks) {
    int blk = blockIdx.x, tid = threadIdx.x;
    int base = blk * 1024 + tid * 4;
    float4 r = *(const float4*)(rewards + base);
    int4   m = *(const int4*)(masks + base);
    float a = 1.f, b = 0.f, c;
    c = GAMMA * (float)m.w; b = r.w + c * b; a *= c;
    c = GAMMA * (float)m.z; b = r.z + c * b; a *= c;
    c = GAMMA * (float)m.y; b = r.y + c * b; a *= c;
    c = GAMMA * (float)m.x; b = r.x + c * b; a *= c;
    __shared__ float sa[256], sb[256];
    sa[tid] = a; sb[tid] = b;
    __syncthreads();
    if (tid == 0) {
        float Ab = 1.f, Bb = 0.f;
        for (int t = 255; t >= 0; --t) { Bb = sb[t] + sa[t] * Bb; Ab = sa[t] * Ab; }
        g_blockA[blk] = Ab; g_blockB[blk] = Bb;
    }
}

// ---------------- K2: scan the 256 block summaries (right to left) ----------------
__global__ void k_scan2() {
    __shared__ float sa[256], sb[256], sinc[256];
    int tid = threadIdx.x;
    sa[tid] = g_blockA[tid]; sb[tid] = g_blockB[tid];
    __syncthreads();
    if (tid == 0) {
        float x = 0.f;
        for (int b = 255; b >= 0; --b) { sinc[b] = x; x = sb[b] + sa[b] * x; }
    }
    __syncthreads();
    g_blockInc[tid] = sinc[tid];
}

// ---------------- K3: apply scan, compute adv, accumulate sums ----------------
__global__ void k_scan3(const float* __restrict__ rewards, const int* __restrict__ masks,
                        const float* __restrict__ values) {
    int blk = blockIdx.x, tid = threadIdx.x;
    int base = blk * 1024 + tid * 4;
    float4 r = *(const float4*)(rewards + base);
    int4   m = *(const int4*)(masks + base);
    float c0 = GAMMA * (float)m.x, c1 = GAMMA * (float)m.y;
    float c2 = GAMMA * (float)m.z, c3 = GAMMA * (float)m.w;
    float a = 1.f, b = 0.f;
    b = r.w + c3 * b; a *= c3;
    b = r.z + c2 * b; a *= c2;
    b = r.y + c1 * b; a *= c1;
    b = r.x + c0 * b; a *= c0;
    __shared__ float sa[256], sb[256], sinc[256];
    __shared__ float red8[8];
    sa[tid] = a; sb[tid] = b;
    __syncthreads();
    if (tid == 0) {
        float x = g_blockInc[blk];
        for (int t = 255; t >= 0; --t) { sinc[t] = x; x = sb[t] + sa[t] * x; }
    }
    __syncthreads();
    float x = sinc[tid];
    float ret3 = r.w + c3 * x;
    float ret2 = r.z + c2 * ret3;
    float ret1 = r.y + c1 * ret2;
    float ret0 = r.x + c0 * ret1;
    float4 v = *(const float4*)(values + base);
    float4 adv = make_float4(ret0 - v.x, ret1 - v.y, ret2 - v.z, ret3 - v.w);
    *(float4*)(g_adv + base) = adv;
    float s1 = adv.x + adv.y + adv.z + adv.w;
    float s2 = adv.x * adv.x + adv.y * adv.y + adv.z * adv.z + adv.w * adv.w;
    float t1 = block_reduce_256(s1, red8);
    __syncthreads();
    float t2 = block_reduce_256(s2, red8);
    if (tid == 0) { atomicAdd(&g_s1, t1); atomicAdd(&g_s2, t2); }
}

// ---------------- K4: stats ----------------
__global__ void k_stats() {
    float s1 = g_s1, s2 = g_s2;
    float mean = s1 / (float)T;
    float var  = (s2 - s1 * mean) / (float)(T - 1);
    g_mean = mean;
    g_inv  = 1.f / (sqrtf(var) + 1e-7f);
    g_critic = s2 / (float)T;
}

// ---------------- K5: fused policy-net + PPO actor loss ----------------
static constexpr int RT = 256;       // rows per CTA tile
static constexpr int NH = 64;        // H chunk
static constexpr int NCHUNK = H / NH;
static constexpr int LDA = 136;      // half elems
static constexpr int LDW = 72;
static constexpr int LDP = 72;
static constexpr int LDMU = 20;      // float elems (reduces epilogue bank conflicts)

static constexpr int SM_A   = 0;
static constexpr int SM_W1  = SM_A   + RT * LDA * 2;       // 69632
static constexpr int SM_P   = SM_W1  + 128 * LDW * 2;      // 88064
static constexpr int SM_TMP = SM_P   + RT * LDP * 2;       // 124928
static constexpr int SM_WMU = SM_TMP + 8 * 256 * 4;        // 133120
static constexpr int SM_WLV = SM_WMU + 64 * 16 * 2;        // 135168
static constexpr int SM_B1  = SM_WLV + 64 * 16 * 2;        // 137216
static constexpr int SM_TOTAL = SM_B1 + 64 * 4;            // 137472

__global__ __launch_bounds__(256, 1)
void k_main(const float* __restrict__ states, const float* __restrict__ actions,
            const float* __restrict__ blp,
            const float* __restrict__ W1, const float* __restrict__ b1,
            const float* __restrict__ Wmu, const float* __restrict__ bmu,
            const float* __restrict__ Wlv, const float* __restrict__ blv) {
    extern __shared__ char smem[];
    half*  sA   = (half*)(smem + SM_A);
    half*  sW1  = (half*)(smem + SM_W1);
    half*  sP   = (half*)(smem + SM_P);
    float* sTmp = (float*)(smem + SM_TMP);
    half*  sWmu = (half*)(smem + SM_WMU);
    half*  sWlv = (half*)(smem + SM_WLV);
    float* sB1  = (float*)(smem + SM_B1);
    float* sMu  = (float*)(smem + SM_A);        // overlays sA after chunk loop
    float* sLv  = sMu + RT * LDMU;
    __shared__ float red8[8];

    int tid  = threadIdx.x;
    int warp = tid >> 5, lane = tid & 31;
    int r0   = blockIdx.x * RT;

    // load states tile [256 x 128] -> fp16
    #pragma unroll
    for (int it = 0; it < 32; ++it) {
        int idx = tid + 256 * it;           // 8192 float4
        int row = idx >> 5;                 // 32 float4 per row
        int c4  = idx & 31;
        float4 v = *(const float4*)(states + (size_t)(r0 + row) * S + c4 * 4);
        half2* dst = (half2*)(sA + row * LDA + c4 * 4);
        dst[0] = __floats2half2_rn(v.x, v.y);
        dst[1] = __floats2half2_rn(v.z, v.w);
    }

    wmma::fragment<wmma::accumulator, 16, 16, 16, float> accMu[2], accLv[2];
    wmma::fill_fragment(accMu[0], 0.f); wmma::fill_fragment(accMu[1], 0.f);
    wmma::fill_fragment(accLv[0], 0.f); wmma::fill_fragment(accLv[1], 0.f);

    for (int ch = 0; ch < NCHUNK; ++ch) {
        __syncthreads();   // protect sW1/sWmu/sWlv from previous-iteration readers
        // W1 chunk [128 x 64] -> fp16
        #pragma unroll
        for (int it = 0; it < 8; ++it) {
            int idx = tid + 256 * it;       // 2048 float4
            int row = idx >> 4;
            int c4  = idx & 15;
            float4 v = *(const float4*)(W1 + (size_t)row * H + ch * NH + c4 * 4);
            half2* dst = (half2*)(sW1 + row * LDW + c4 * 4);
            dst[0] = __floats2half2_rn(v.x, v.y);
            dst[1] = __floats2half2_rn(v.z, v.w);
        }
        // W_mu / W_lv chunks [64 x 16]
        {
            int row = tid >> 2, c4 = tid & 3;
            float4 v = *(const float4*)(Wmu + (size_t)(ch * NH + row) * A + c4 * 4);
            half2* dm = (half2*)(sWmu + row * 16 + c4 * 4);
            dm[0] = __floats2half2_rn(v.x, v.y);
            dm[1] = __floats2half2_rn(v.z, v.w);
            float4 u = *(const float4*)(Wlv + (size_t)(ch * NH + row) * A + c4 * 4);
            half2* dl = (half2*)(sWlv + row * 16 + c4 * 4);
            dl[0] = __floats2half2_rn(u.x, u.y);
            dl[1] = __floats2half2_rn(u.z, u.w);
        }
        if (tid < 64) sB1[tid] = b1[ch * NH + tid];
        __syncthreads();

        // GEMM1: P = tanh(states @ W1chunk + b1chunk)  [256 x 64]
        #pragma unroll
        for (int j = 0; j < 8; ++j) {
            int tt = warp + 8 * j;
            int tr = tt & 15, tc = tt >> 4;
            wmma::fragment<wmma::accumulator, 16, 16, 16, float> acc;
            wmma::fill_fragment(acc, 0.f);
            #pragma unroll
            for (int k = 0; k < 8; ++k) {
                wmma::fragment<wmma::matrix_a, 16, 16, 16, half, wmma::row_major> fa;
                wmma::fragment<wmma::matrix_b, 16, 16, 16, half, wmma::row_major> fb;
                wmma::load_matrix_sync(fa, sA + tr * 16 * LDA + k * 16, LDA);
                wmma::load_matrix_sync(fb, sW1 + k * 16 * LDW + tc * 16, LDW);
                wmma::mma_sync(acc, fa, fb, acc);
            }
            wmma::store_matrix_sync(sTmp + warp * 256, acc, 16, wmma::mem_row_major);
            __syncwarp();
            #pragma unroll
            for (int i = 0; i < 8; ++i) {
                int pos = lane + 32 * i;
                int rr = pos >> 4, cc = pos & 15;
                float v = sTmp[warp * 256 + pos] + sB1[tc * 16 + cc];
                sP[(tr * 16 + rr) * LDP + tc * 16 + cc] = __float2half_rn(tanh_fast(v));
            }
            __syncwarp();
        }
        __syncthreads();   // sP complete

        // GEMM2: mu/lv += P @ Wchunk   [256 x 16]
        #pragma unroll
        for (int q = 0; q < 2; ++q) {
            int rt2 = warp * 2 + q;
            #pragma unroll
            for (int k = 0; k < 4; ++k) {
                wmma::fragment<wmma::matrix_a, 16, 16, 16, half, wmma::row_major> fa;
                wmma::fragment<wmma::matrix_b, 16, 16, 16, half, wmma::row_major> fb;
                wmma::load_matrix_sync(fa, sP + rt2 * 16 * LDP + k * 16, LDP);
                wmma::load_matrix_sync(fb, sWmu + k * 16 * 16, 16);
                wmma::mma_sync(accMu[q], fa, fb, accMu[q]);
                wmma::load_matrix_sync(fb, sWlv + k * 16 * 16, 16);
                wmma::mma_sync(accLv[q], fa, fb, accLv[q]);
            }
        }
    }
    __syncthreads();

    // dump mu/lv to smem (overlaying sA, which is dead now)
    #pragma unroll
    for (int q = 0; q < 2; ++q) {
        int rt2 = warp * 2 + q;
        wmma::store_matrix_sync(sMu + rt2 * 16 * LDMU, accMu[q], LDMU, wmma::mem_row_major);
        wmma::store_matrix_sync(sLv + rt2 * 16 * LDMU, accLv[q], LDMU, wmma::mem_row_major);
    }
    if (tid < 16) { sTmp[tid] = bmu[tid]; sTmp[16 + tid] = blv[tid]; }
    __syncthreads();

    // epilogue: one row per thread
    int gr = r0 + tid;
    const float4* a4 = (const float4*)(actions + (size_t)gr * A);
    const float4* p4 = (const float4*)(blp + (size_t)gr * A);
    float lsum = 0.f;
    #pragma unroll
    for (int q = 0; q < 4; ++q) {
        float4 av = a4[q];
        float4 bv = p4[q];
        float aarr[4] = {av.x, av.y, av.z, av.w};
        float barr[4] = {bv.x, bv.y, bv.z, bv.w};
        #pragma unroll
        for (int j = 0; j < 4; ++j) {
            int col = q * 4 + j;
            float mu = sMu[tid * LDMU + col] + sTmp[col];
            float lv = sLv[tid * LDMU + col] + sTmp[16 + col];
            float d  = aarr[j] - mu;
            float logp = -0.5f * d * d * __expf(-lv) - 0.5f * lv - LOG_SQRT_2PI;
            lsum += logp - barr[j];
        }
    }
    float ratio = __expf(lsum);
    float ahat  = (g_adv[gr] - g_mean) * g_inv;
    float rc    = fminf(fmaxf(ratio, 1.f - EPSC), 1.f + EPSC);
    float term  = fminf(ratio * ahat, rc * ahat);

    float bsum = block_reduce_256(term, red8);
    if (tid == 0) atomicAdd(&g_actor, bsum);
}

// ---------------- K6: final scalar ----------------
__global__ void k_final(float* out) {
    out[0] = g_critic - g_actor / (float)T;
}

// ---------------- launch ----------------
extern "C" void kernel_launch(void* const* d_in, const int* in_sizes, int n_in,
                              void* d_out, int out_size) {
    const float* states  = (const float*)d_in[0];
    const float* actions = (const float*)d_in[1];
    const float* rewards = (const float*)d_in[2];
    const float* values  = (const float*)d_in[3];
    const float* blp     = (const float*)d_in[4];
    const float* W1      = (const float*)d_in[5];
    const float* b1      = (const float*)d_in[6];
    const float* Wmu     = (const float*)d_in[7];
    const float* bmu     = (const float*)d_in[8];
    const float* Wlv     = (const float*)d_in[9];
    const float* blv     = (const float*)d_in[10];
    const int*   masks   = (const int*)d_in[11];

    cudaFuncSetAttribute(k_main, cudaFuncAttributeMaxDynamicSharedMemorySize, SM_TOTAL);

    k_zero<<<1, 1>>>();
    k_scan1<<<256, 256>>>(rewards, masks);
    k_scan2<<<1, 256>>>();
    k_scan3<<<256, 256>>>(rewards, masks, values);
    k_stats<<<1, 1>>>();
    k_main<<<T / RT, 256, SM_TOTAL>>>(states, actions, blp, W1, b1, Wmu, bmu, Wlv, blv);
    k_final<<<1, 1>>>((float*)d_out);
}